// round 15
// baseline (speedup 1.0000x reference)
#include <cuda_runtime.h>
#include <cuda_fp16.h>
#include <cstdint>
#include <cstddef>
#include <math.h>

#define NN 50000
#define EE 800000
#define FF 128
#define HH 8
#define CC 16
#define NLAY 5
#define GNFREQ 3
#define ETOT (EE + NN)

#define XP 136
#define WROW 132
#define LROW 68
#define SB 512
#define NSCANB ((NN + SB - 1) / SB)

// ---------------- device scratch ----------------
__device__ float  g_x[NN * FF];      // fp32 residual stream (fp16 failed: 2.9e-3)
__device__ __half g_hh[NN * FF];
__device__ float  g_as[NN * HH];
__device__ float  g_ad[NN * HH];
__device__ float  g_sagg[NN];
__device__ float  g_dinv[NN];
__device__ float  g_p[NN];
__device__ int    g_rowptr[NN + 1];
__device__ int    g_deg[NN];
__device__ int    g_cursor[NN];
__device__ int    g_col[ETOT];
__device__ float  g_s1[2 * FF];
__device__ float  g_s2[2 * FF];
__device__ int    g_bsum[NSCANB + 1];
__device__ uint4  g_wpack4[NLAY * 32 * WROW / 2];
__device__ uint4  g_lpack4[32 * LROW / 2];

// ---------------- GN coefficient helper (identical math everywhere) ----------
__device__ __forceinline__ void gn_coef(int f, int grp, int n,
                                        const float* gnw, const float* gnb,
                                        const float* gns, float& ml, float& ad) {
    float invn = 1.0f / (float)n;
    float mu = g_s1[grp * FF + f] * invn;
    float m2 = g_s2[grp * FF + f] * invn;
    float mum = gns[f] * mu;
    float var = m2 - 2.f * mum * mu + mum * mum;
    float inv = rsqrtf(var + 1e-5f);
    ml = gnw[f] * inv;
    ad = gnb[f] - mum * ml;
}

// ---------------- weight pre-pack + scratch zero (merged) ----------------
__global__ void k_wpack(const float* __restrict__ gat_w, const float* __restrict__ lin_w,
                        int n) {
    int i = blockIdx.x * blockDim.x + threadIdx.x;
    if (i < n) g_deg[i] = 0;
    if (i < 2 * FF) { g_s1[i] = 0.f; g_s2[i] = 0.f; }
    if (i < NLAY * 32 * 128) {
        int l = i / (32 * 128);
        int r = (i / 128) & 31;
        int c = i & 127;
        int k0 = 16 * (r >> 2) + 2 * (r & 3);
        const float* W = gat_w + (size_t)l * FF * FF;
        __half2 lo = __floats2half2_rn(W[k0 * FF + c], W[(k0 + 1) * FF + c]);
        __half2 hi = __floats2half2_rn(W[(k0 + 8) * FF + c], W[(k0 + 9) * FF + c]);
        uint2 pk;
        pk.x = *(unsigned*)&lo;
        pk.y = *(unsigned*)&hi;
        ((uint2*)g_wpack4)[l * 32 * WROW + r * WROW + c] = pk;
    } else if (i < NLAY * 32 * 128 + 32 * 64) {
        int i2 = i - NLAY * 32 * 128;
        int r = i2 >> 6, c = i2 & 63;
        int k0 = 16 * (r >> 2) + 2 * (r & 3);
        __half2 lo = __floats2half2_rn(lin_w[k0 * 64 + c], lin_w[(k0 + 1) * 64 + c]);
        __half2 hi = __floats2half2_rn(lin_w[(k0 + 8) * 64 + c], lin_w[(k0 + 9) * 64 + c]);
        uint2 pk;
        pk.x = *(unsigned*)&lo;
        pk.y = *(unsigned*)&hi;
        ((uint2*)g_lpack4)[r * LROW + c] = pk;
    }
}

// ---------------- CSR build ----------------
__global__ void k_deg_edges(const int* __restrict__ dst, int e) {
    int i = blockIdx.x * blockDim.x + threadIdx.x;
    if (i < e) atomicAdd(&g_deg[dst[i]], 1);
}

__global__ void k_scan1(int n) {
    __shared__ int ws[SB / 32];
    int tid = threadIdx.x, lane = tid & 31, warp = tid >> 5;
    int i = blockIdx.x * SB + tid;
    int v = (i < n) ? (g_deg[i] + 1) : 0;
#pragma unroll
    for (int o = 16; o > 0; o >>= 1) v += __shfl_xor_sync(0xffffffffu, v, o);
    if (lane == 0) ws[warp] = v;
    __syncthreads();
    if (warp == 0) {
        int s = (lane < SB / 32) ? ws[lane] : 0;
#pragma unroll
        for (int o = 16; o > 0; o >>= 1) s += __shfl_xor_sync(0xffffffffu, s, o);
        if (lane == 0) g_bsum[blockIdx.x] = s;
    }
}

__global__ void k_scan3(const float* __restrict__ sig, int n, int nblk) {
    __shared__ int ws[SB / 32];
    __shared__ int s_off;
    int tid = threadIdx.x, lane = tid & 31, warp = tid >> 5;
    int i = blockIdx.x * SB + tid;
    int v = (i < n) ? (g_deg[i] + 1) : 0;
    int x = v;
#pragma unroll
    for (int o = 1; o < 32; o <<= 1) {
        int t = __shfl_up_sync(0xffffffffu, x, o);
        if (lane >= o) x += t;
    }
    if (lane == 31) ws[warp] = x;
    if (warp == (SB / 32) - 1) {
        int off = 0;
        for (int j = lane; j < nblk; j += 32)
            if (j < blockIdx.x) off += g_bsum[j];
#pragma unroll
        for (int o = 16; o > 0; o >>= 1) off += __shfl_xor_sync(0xffffffffu, off, o);
        if (lane == 0) s_off = off;
    }
    __syncthreads();
    if (warp == 0) {
        int y = (lane < SB / 32) ? ws[lane] : 0;
#pragma unroll
        for (int o = 1; o < 32; o <<= 1) {
            int t = __shfl_up_sync(0xffffffffu, y, o);
            if (lane >= o) y += t;
        }
        if (lane < SB / 32) ws[lane] = y;
    }
    __syncthreads();
    int excl = x - v + ((warp == 0) ? 0 : ws[warp - 1]) + s_off;
    if (i < n) {
        g_rowptr[i] = excl;
        g_col[excl] = i;
        g_cursor[i] = excl + 1;
        float di = rsqrtf((float)v);
        g_dinv[i] = di;
        g_p[i] = di * sig[i];
    }
    if (blockIdx.x == nblk - 1 && tid == SB - 1) g_rowptr[n] = excl + v;
}

__global__ void k_fill(const int* __restrict__ src, const int* __restrict__ dst, int e) {
    int i = blockIdx.x * blockDim.x + threadIdx.x;
    if (i < e) {
        int p = atomicAdd(&g_cursor[dst[i]], 1);
        g_col[p] = src[i];
    }
}

// ---------------- GCN (rank-1 collapse) ----------------
__global__ void k_gcn_agg(int n) {
    int i = blockIdx.x * blockDim.x + threadIdx.x;
    if (i >= n) return;
    int beg = g_rowptr[i], end = g_rowptr[i + 1];
    float s = 0.f;
    for (int j = beg; j < end; j++) s += g_p[g_col[j]];
    g_sagg[i] = s * g_dinv[i];
}

__global__ void k_gcn_x(const float* __restrict__ w, const float* __restrict__ b, int n) {
    int f = threadIdx.x;
    float wf = w[f], bf = b[f];
    int base = blockIdx.x * 64;
    float s1 = 0.f, s2 = 0.f;
    for (int r = 0; r < 64; r++) {
        int nd = base + r;
        if (nd >= n) break;
        float v = fmaxf(fmaf(g_sagg[nd], wf, bf), 0.f);
        g_x[nd * FF + f] = v;
        s1 += v;
        s2 += v * v;
    }
    atomicAdd(&g_s1[f], s1);
    atomicAdd(&g_s2[f], s2);
}

// ---------------- tensor-core helpers ----------------
__device__ __forceinline__ void mma16816(float c[4], unsigned a0, unsigned a1,
                                         unsigned a2, unsigned a3,
                                         unsigned b0, unsigned b1) {
    asm volatile(
        "mma.sync.aligned.m16n8k16.row.col.f32.f16.f16.f32 "
        "{%0,%1,%2,%3}, {%4,%5,%6,%7}, {%8,%9}, {%0,%1,%2,%3};"
        : "+f"(c[0]), "+f"(c[1]), "+f"(c[2]), "+f"(c[3])
        : "r"(a0), "r"(a1), "r"(a2), "r"(a3), "r"(b0), "r"(b1));
}

__device__ __forceinline__ void ldsm4(unsigned& a0, unsigned& a1, unsigned& a2,
                                      unsigned& a3, unsigned addr) {
    asm volatile("ldmatrix.sync.aligned.m8n8.x4.shared.b16 {%0,%1,%2,%3}, [%4];"
                 : "=r"(a0), "=r"(a1), "=r"(a2), "=r"(a3)
                 : "r"(addr));
}

// ---------------- layer GEMM: h = x @ W, fused GN-apply + attention coefs -----
// GN layers: normalize while loading into Xs only (NO writeback — k_attn
// re-applies the identical transform on its residual read; bit-exact).
template <int GN>
__global__ void k_mm(int layer,
                     const float* __restrict__ atts, const float* __restrict__ attd,
                     const float* __restrict__ gnw, const float* __restrict__ gnb,
                     const float* __restrict__ gns, int grp, int n) {
    extern __shared__ char smem[];
    __half* Xs = (__half*)smem;
    __half* Wsh = (__half*)(smem + 128 * XP * 2);
    float* sm_mul = (float*)(smem + 128 * XP * 2 + 33792);
    float* sm_add = sm_mul + FF;
    const uint2* Wp = (const uint2*)Wsh;

    int tid = threadIdx.x;
    int blockRow = blockIdx.x * 128;

    if (GN) {
        if (tid < FF) {
            float ml, ad;
            gn_coef(tid, grp, n, gnw, gnb, gns, ml, ad);
            sm_mul[tid] = ml;
            sm_add[tid] = ad;
        }
        __syncthreads();
    }

    {
        const uint4* gw = g_wpack4 + layer * (32 * WROW / 2);
        uint4* ws4 = (uint4*)Wsh;
        for (int i = tid; i < 32 * WROW / 2; i += 256) ws4[i] = gw[i];
    }

    for (int i = tid; i < 128 * 32; i += 256) {
        int row = i >> 5, c4 = i & 31;
        int node = blockRow + row;
        float4 v = make_float4(0.f, 0.f, 0.f, 0.f);
        if (node < n) {
            v = ((const float4*)(g_x + (size_t)node * FF))[c4];
            if (GN) {
                int f = c4 * 4;
                v.x = v.x * sm_mul[f + 0] + sm_add[f + 0];
                v.y = v.y * sm_mul[f + 1] + sm_add[f + 1];
                v.z = v.z * sm_mul[f + 2] + sm_add[f + 2];
                v.w = v.w * sm_mul[f + 3] + sm_add[f + 3];
            }
        }
        __half2 p0 = __floats2half2_rn(v.x, v.y);
        __half2 p1 = __floats2half2_rn(v.z, v.w);
        uint2 pk;
        pk.x = *(unsigned*)&p0;
        pk.y = *(unsigned*)&p1;
        *(uint2*)(Xs + row * XP + c4 * 4) = pk;
    }
    __syncthreads();

    int warp = tid >> 5, lane = tid & 31;
    int warp_m = warp >> 2, warp_n = warp & 3;
    int colbase = warp_n * 32;

    float c[4][4][4];
#pragma unroll
    for (int a = 0; a < 4; a++)
#pragma unroll
        for (int bq = 0; bq < 4; bq++)
#pragma unroll
            for (int d = 0; d < 4; d++) c[a][bq][d] = 0.f;

    unsigned xs_base = (unsigned)__cvta_generic_to_shared(Xs);
    int lrow_add = ((lane >> 3) & 1) * 8 + (lane & 7);
    int lcol_b = (lane >> 4) * 16;

#pragma unroll
    for (int s = 0; s < 8; s++) {
        unsigned a[4][4];
#pragma unroll
        for (int mi = 0; mi < 4; mi++) {
            unsigned addr = xs_base +
                (warp_m * 64 + mi * 16 + lrow_add) * (XP * 2) + s * 32 + lcol_b;
            ldsm4(a[mi][0], a[mi][1], a[mi][2], a[mi][3], addr);
        }
        uint2 bb[4];
#pragma unroll
        for (int ni = 0; ni < 4; ni++)
            bb[ni] = Wp[(s * 4 + (lane & 3)) * WROW + colbase + ni * 8 + (lane >> 2)];
#pragma unroll
        for (int mi = 0; mi < 4; mi++)
#pragma unroll
            for (int ni = 0; ni < 4; ni++)
                mma16816(c[mi][ni], a[mi][0], a[mi][1], a[mi][2], a[mi][3],
                         bb[ni].x, bb[ni].y);
    }

    float2 aS[4], aD[4];
#pragma unroll
    for (int ni = 0; ni < 4; ni++) {
        int c2 = (colbase >> 1) + ni * 4 + (lane & 3);
        aS[ni] = ((const float2*)atts)[c2];
        aD[ni] = ((const float2*)attd)[c2];
    }
    int hd0 = colbase >> 4;

#pragma unroll
    for (int mi = 0; mi < 4; mi++) {
        int grA = blockRow + warp_m * 64 + mi * 16 + (lane >> 2);
        int grB = grA + 8;
        int col0 = colbase + (lane & 3) * 2;
        if (grA < n) {
            __half* hp = g_hh + (size_t)grA * FF + col0;
#pragma unroll
            for (int ni = 0; ni < 4; ni++) {
                __half2 hv = __floats2half2_rn(c[mi][ni][0], c[mi][ni][1]);
                *(__half2*)(hp + ni * 8) = hv;
            }
        }
        if (grB < n) {
            __half* hp = g_hh + (size_t)grB * FF + col0;
#pragma unroll
            for (int ni = 0; ni < 4; ni++) {
                __half2 hv = __floats2half2_rn(c[mi][ni][2], c[mi][ni][3]);
                *(__half2*)(hp + ni * 8) = hv;
            }
        }
        float sAL = c[mi][0][0] * aS[0].x + c[mi][0][1] * aS[0].y +
                    c[mi][1][0] * aS[1].x + c[mi][1][1] * aS[1].y;
        float sAR = c[mi][2][0] * aS[2].x + c[mi][2][1] * aS[2].y +
                    c[mi][3][0] * aS[3].x + c[mi][3][1] * aS[3].y;
        float sBL = c[mi][0][2] * aS[0].x + c[mi][0][3] * aS[0].y +
                    c[mi][1][2] * aS[1].x + c[mi][1][3] * aS[1].y;
        float sBR = c[mi][2][2] * aS[2].x + c[mi][2][3] * aS[2].y +
                    c[mi][3][2] * aS[3].x + c[mi][3][3] * aS[3].y;
        float dAL = c[mi][0][0] * aD[0].x + c[mi][0][1] * aD[0].y +
                    c[mi][1][0] * aD[1].x + c[mi][1][1] * aD[1].y;
        float dAR = c[mi][2][0] * aD[2].x + c[mi][2][1] * aD[2].y +
                    c[mi][3][0] * aD[3].x + c[mi][3][1] * aD[3].y;
        float dBL = c[mi][0][2] * aD[0].x + c[mi][0][3] * aD[0].y +
                    c[mi][1][2] * aD[1].x + c[mi][1][3] * aD[1].y;
        float dBR = c[mi][2][2] * aD[2].x + c[mi][2][3] * aD[2].y +
                    c[mi][3][2] * aD[3].x + c[mi][3][3] * aD[3].y;
#pragma unroll
        for (int o = 1; o < 4; o <<= 1) {
            sAL += __shfl_xor_sync(0xffffffffu, sAL, o);
            sAR += __shfl_xor_sync(0xffffffffu, sAR, o);
            sBL += __shfl_xor_sync(0xffffffffu, sBL, o);
            sBR += __shfl_xor_sync(0xffffffffu, sBR, o);
            dAL += __shfl_xor_sync(0xffffffffu, dAL, o);
            dAR += __shfl_xor_sync(0xffffffffu, dAR, o);
            dBL += __shfl_xor_sync(0xffffffffu, dBL, o);
            dBR += __shfl_xor_sync(0xffffffffu, dBR, o);
        }
        if ((lane & 3) == 0) {
            if (grA < n) {
                g_as[grA * HH + hd0] = sAL;
                g_as[grA * HH + hd0 + 1] = sAR;
                g_ad[grA * HH + hd0] = dAL;
                g_ad[grA * HH + hd0 + 1] = dAR;
            }
            if (grB < n) {
                g_as[grB * HH + hd0] = sBL;
                g_as[grB * HH + hd0 + 1] = sBR;
                g_ad[grB * HH + hd0] = dBL;
                g_ad[grB * HH + hd0 + 1] = dBR;
            }
        }
    }
}

// ---------------- output projection ----------------
__global__ void k_lin(const float* __restrict__ b, float* __restrict__ out, int n) {
    extern __shared__ char smem[];
    __half* Xs = (__half*)smem;
    __half* Wsh = (__half*)(smem + 128 * XP * 2);
    const uint2* Wp = (const uint2*)Wsh;
    int tid = threadIdx.x;
    int blockRow = blockIdx.x * 128;

    {
        uint4* ws4 = (uint4*)Wsh;
        for (int i = tid; i < 32 * LROW / 2; i += 256) ws4[i] = g_lpack4[i];
    }

    for (int i = tid; i < 128 * 32; i += 256) {
        int row = i >> 5, c4 = i & 31;
        int node = blockRow + row;
        float4 v = make_float4(0.f, 0.f, 0.f, 0.f);
        if (node < n) v = ((const float4*)(g_x + (size_t)node * FF))[c4];
        __half2 p0 = __floats2half2_rn(v.x, v.y);
        __half2 p1 = __floats2half2_rn(v.z, v.w);
        uint2 pk;
        pk.x = *(unsigned*)&p0;
        pk.y = *(unsigned*)&p1;
        *(uint2*)(Xs + row * XP + c4 * 4) = pk;
    }
    __syncthreads();

    int warp = tid >> 5, lane = tid & 31;
    int warp_m = warp >> 1, warp_n = warp & 1;
    int colbase = warp_n * 32;

    float c[2][4][4];
#pragma unroll
    for (int a = 0; a < 2; a++)
#pragma unroll
        for (int bq = 0; bq < 4; bq++)
#pragma unroll
            for (int d = 0; d < 4; d++) c[a][bq][d] = 0.f;

    unsigned xs_base = (unsigned)__cvta_generic_to_shared(Xs);
    int lrow_add = ((lane >> 3) & 1) * 8 + (lane & 7);
    int lcol_b = (lane >> 4) * 16;

#pragma unroll
    for (int s = 0; s < 8; s++) {
        unsigned a[2][4];
#pragma unroll
        for (int mi = 0; mi < 2; mi++) {
            unsigned addr = xs_base +
                (warp_m * 32 + mi * 16 + lrow_add) * (XP * 2) + s * 32 + lcol_b;
            ldsm4(a[mi][0], a[mi][1], a[mi][2], a[mi][3], addr);
        }
        uint2 bb[4];
#pragma unroll
        for (int ni = 0; ni < 4; ni++)
            bb[ni] = Wp[(s * 4 + (lane & 3)) * LROW + colbase + ni * 8 + (lane >> 2)];
#pragma unroll
        for (int mi = 0; mi < 2; mi++)
#pragma unroll
            for (int ni = 0; ni < 4; ni++)
                mma16816(c[mi][ni], a[mi][0], a[mi][1], a[mi][2], a[mi][3],
                         bb[ni].x, bb[ni].y);
    }

#pragma unroll
    for (int mi = 0; mi < 2; mi++) {
        int grA = blockRow + warp_m * 32 + mi * 16 + (lane >> 2);
        int grB = grA + 8;
        int col0 = colbase + (lane & 3) * 2;
#pragma unroll
        for (int ni = 0; ni < 4; ni++) {
            float2 bv = ((const float2*)b)[(col0 + ni * 8) >> 1];
            if (grA < n) {
                float2 o = make_float2(c[mi][ni][0] + bv.x, c[mi][ni][1] + bv.y);
                *(float2*)(out + (size_t)grA * 64 + col0 + ni * 8) = o;
            }
            if (grB < n) {
                float2 o = make_float2(c[mi][ni][2] + bv.x, c[mi][ni][3] + bv.y);
                *(float2*)(out + (size_t)grB * 64 + col0 + ni * 8) = o;
            }
        }
    }
}

// ---------------- edge softmax + aggregation + residual ----------------------
// GNRES: apply the (bit-identical) GN transform to the residual x on read,
// replacing k_mm's eliminated writeback.
template <int STATS, int GNRES>
__global__ void k_attn(const float* __restrict__ gb,
                       const float* __restrict__ gnw, const float* __restrict__ gnb,
                       const float* __restrict__ gns, int grp, int n) {
    __shared__ float bsum[FF];
    __shared__ float bsq[FF];
    __shared__ float smul[FF];
    __shared__ float sadd[FF];
    int tid = threadIdx.x;
    int warp = tid >> 5, lane = tid & 31;
    int node = blockIdx.x * 8 + warp;

    if (STATS) {
        if (tid < FF) { bsum[tid] = 0.f; bsq[tid] = 0.f; }
    }
    if (GNRES) {
        if (tid < FF) {
            float ml, ad;
            gn_coef(tid, grp, n, gnw, gnb, gns, ml, ad);
            smul[tid] = ml;
            sadd[tid] = ad;
        }
    }
    if (STATS || GNRES) __syncthreads();

    int half = lane >> 4, fl = lane & 15;
    int hd = fl >> 1;
    int f0 = fl * 8 + half * 4;

    float4 xv = {0, 0, 0, 0};
    if (node < n) {
        int beg = g_rowptr[node], end = g_rowptr[node + 1];
        float adh = g_ad[node * HH + hd];

        float s = 0.f;
        float acc[8] = {0.f, 0.f, 0.f, 0.f, 0.f, 0.f, 0.f, 0.f};
        for (int jb = beg; jb < end; jb += 2) {
            int j = jb + half;
            bool valid = (j < end);
            int u = valid ? g_col[j] : node;
            float ev = g_as[u * HH + hd] + adh;
            ev = ev > 0.f ? ev : 0.2f * ev;
            float w = valid ? __expf(ev) : 0.f;
            float4 hv4 = *(const float4*)(g_hh + (size_t)u * FF + fl * 8);
            const __half2* hp = (const __half2*)&hv4;
            s += w;
#pragma unroll
            for (int q = 0; q < 4; q++) {
                float2 f = __half22float2(hp[q]);
                acc[2 * q + 0] += w * f.x;
                acc[2 * q + 1] += w * f.y;
            }
        }

        s += __shfl_xor_sync(0xffffffffu, s, 16);
#pragma unroll
        for (int q = 0; q < 8; q++)
            acc[q] += __shfl_xor_sync(0xffffffffu, acc[q], 16);
        float rd = 1.0f / s;

        float4 b4 = *(const float4*)(gb + f0);
        float* xp = g_x + (size_t)node * FF + f0;
        xv = *(float4*)xp;
        if (GNRES) {
            xv.x = xv.x * smul[f0 + 0] + sadd[f0 + 0];
            xv.y = xv.y * smul[f0 + 1] + sadd[f0 + 1];
            xv.z = xv.z * smul[f0 + 2] + sadd[f0 + 2];
            xv.w = xv.w * smul[f0 + 3] + sadd[f0 + 3];
        }
        int o = half * 4;
        xv.x += fmaxf(acc[o + 0] * rd + b4.x, 0.f);
        xv.y += fmaxf(acc[o + 1] * rd + b4.y, 0.f);
        xv.z += fmaxf(acc[o + 2] * rd + b4.z, 0.f);
        xv.w += fmaxf(acc[o + 3] * rd + b4.w, 0.f);
        *(float4*)xp = xv;
    }

    if (STATS) {
        if (node < n) {
            atomicAdd(&bsum[f0 + 0], xv.x); atomicAdd(&bsq[f0 + 0], xv.x * xv.x);
            atomicAdd(&bsum[f0 + 1], xv.y); atomicAdd(&bsq[f0 + 1], xv.y * xv.y);
            atomicAdd(&bsum[f0 + 2], xv.z); atomicAdd(&bsq[f0 + 2], xv.z * xv.z);
            atomicAdd(&bsum[f0 + 3], xv.w); atomicAdd(&bsq[f0 + 3], xv.w * xv.w);
        }
        __syncthreads();
        if (tid < FF) {
            atomicAdd(&g_s1[FF + tid], bsum[tid]);
            atomicAdd(&g_s2[FF + tid], bsq[tid]);
        }
    }
}

// ---------------- launch ----------------
extern "C" void kernel_launch(void* const* d_in, const int* in_sizes, int n_in,
                              void* d_out, int out_size) {
    const float* signals = (const float*)d_in[0];
    const int*   ei      = (const int*)d_in[1];
    const float* gcn_w   = (const float*)d_in[2];
    const float* gcn_b   = (const float*)d_in[3];
    const float* gat_w   = (const float*)d_in[4];
    const float* att_src = (const float*)d_in[5];
    const float* att_dst = (const float*)d_in[6];
    const float* gat_b   = (const float*)d_in[7];
    const float* gn_w    = (const float*)d_in[8];
    const float* gn_b    = (const float*)d_in[9];
    const float* gn_s    = (const float*)d_in[10];
    const float* lin_w   = (const float*)d_in[11];
    const float* lin_b   = (const float*)d_in[12];

    int n = in_sizes[0];
    int e = in_sizes[1] / 2;
    const int* src = ei;
    const int* dst = ei + e;

    const int MM_SMEM = 128 * XP * 2 + 33792 + 2 * FF * 4;  // 69632
    const int LIN_SMEM = 128 * XP * 2 + 17408;              // 52224
    cudaFuncSetAttribute(k_mm<0>, cudaFuncAttributeMaxDynamicSharedMemorySize, MM_SMEM);
    cudaFuncSetAttribute(k_mm<1>, cudaFuncAttributeMaxDynamicSharedMemorySize, MM_SMEM);
    cudaFuncSetAttribute(k_lin, cudaFuncAttributeMaxDynamicSharedMemorySize, LIN_SMEM);

    const int B = 256;
    int nblk = (n + SB - 1) / SB;
    int wz_grid = (n + B - 1) / B;
    k_wpack<<<wz_grid, B>>>(gat_w, lin_w, n);
    k_deg_edges<<<(e + B - 1) / B, B>>>(dst, e);
    k_scan1<<<nblk, SB>>>(n);
    k_scan3<<<nblk, SB>>>(signals, n, nblk);
    k_fill<<<(e + B - 1) / B, B>>>(src, dst, e);

    k_gcn_agg<<<(n + B - 1) / B, B>>>(n);
    k_gcn_x<<<(n + 63) / 64, 128>>>(gcn_w, gcn_b, n);  // + GN group-0 stats

    int grid_mm = (n + 127) / 128;
    int grid_at = (n + 7) / 8;
    for (int i = 0; i < NLAY; i++) {
        const float* aS = att_src + i * HH * CC;
        const float* aD = att_dst + i * HH * CC;
        int isGN = (i % GNFREQ == 0);
        int g = i / GNFREQ;
        if (isGN) {
            k_mm<1><<<grid_mm, 256, MM_SMEM>>>(i, aS, aD, gn_w + g * FF,
                                               gn_b + g * FF, gn_s + g * FF, g, n);
        } else {
            k_mm<0><<<grid_mm, 256, MM_SMEM>>>(i, aS, aD, nullptr, nullptr, nullptr, 0, n);
        }
        const float* gb = gat_b + i * FF;
        if (isGN) {
            // residual must see GN-normalized x (writeback was skipped)
            if (i == 2)
                k_attn<1, 1><<<grid_at, 256>>>(gb, gn_w + g * FF, gn_b + g * FF,
                                               gn_s + g * FF, g, n);
            else
                k_attn<0, 1><<<grid_at, 256>>>(gb, gn_w + g * FF, gn_b + g * FF,
                                               gn_s + g * FF, g, n);
        } else {
            if (i == 2)
                k_attn<1, 0><<<grid_at, 256>>>(gb, nullptr, nullptr, nullptr, 0, n);
            else
                k_attn<0, 0><<<grid_at, 256>>>(gb, nullptr, nullptr, nullptr, 0, n);
        }
    }

    k_lin<<<grid_mm, 256, LIN_SMEM>>>(lin_b, (float*)d_out, n);
}

// round 16
// speedup vs baseline: 1.0215x; 1.0215x over previous
#include <cuda_runtime.h>
#include <cuda_fp16.h>
#include <cstdint>
#include <cstddef>
#include <math.h>

#define NN 50000
#define EE 800000
#define FF 128
#define HH 8
#define CC 16
#define NLAY 5
#define GNFREQ 3
#define ETOT (EE + NN)

#define XP 136
#define WROW 132
#define LROW 68
#define SB 512
#define NSCANB ((NN + SB - 1) / SB)

// ---------------- device scratch ----------------
__device__ float  g_x[NN * FF];      // fp32 residual stream
__device__ __half g_hh[NN * FF];
__device__ float  g_as[NN * HH];
__device__ float  g_ad[NN * HH];
__device__ float  g_sagg[NN];
__device__ float  g_dinv[NN];
__device__ float  g_p[NN];
__device__ int    g_rowptr[NN + 1];
__device__ int    g_deg[NN];
__device__ int    g_cursor[NN];
__device__ int    g_col[ETOT];
__device__ float  g_s1[2 * FF];
__device__ float  g_s2[2 * FF];
__device__ int    g_bsum[NSCANB + 1];
__device__ uint4  g_wpack4[NLAY * 32 * WROW / 2];
__device__ uint4  g_lpack4[32 * LROW / 2];

// ---------------- weight pre-pack + scratch zero (merged) ----------------
__global__ void k_wpack(const float* __restrict__ gat_w, const float* __restrict__ lin_w,
                        int n) {
    int i = blockIdx.x * blockDim.x + threadIdx.x;
    if (i < n) g_deg[i] = 0;
    if (i < 2 * FF) { g_s1[i] = 0.f; g_s2[i] = 0.f; }
    if (i < NLAY * 32 * 128) {
        int l = i / (32 * 128);
        int r = (i / 128) & 31;
        int c = i & 127;
        int k0 = 16 * (r >> 2) + 2 * (r & 3);
        const float* W = gat_w + (size_t)l * FF * FF;
        __half2 lo = __floats2half2_rn(W[k0 * FF + c], W[(k0 + 1) * FF + c]);
        __half2 hi = __floats2half2_rn(W[(k0 + 8) * FF + c], W[(k0 + 9) * FF + c]);
        uint2 pk;
        pk.x = *(unsigned*)&lo;
        pk.y = *(unsigned*)&hi;
        ((uint2*)g_wpack4)[l * 32 * WROW + r * WROW + c] = pk;
    } else if (i < NLAY * 32 * 128 + 32 * 64) {
        int i2 = i - NLAY * 32 * 128;
        int r = i2 >> 6, c = i2 & 63;
        int k0 = 16 * (r >> 2) + 2 * (r & 3);
        __half2 lo = __floats2half2_rn(lin_w[k0 * 64 + c], lin_w[(k0 + 1) * 64 + c]);
        __half2 hi = __floats2half2_rn(lin_w[(k0 + 8) * 64 + c], lin_w[(k0 + 9) * 64 + c]);
        uint2 pk;
        pk.x = *(unsigned*)&lo;
        pk.y = *(unsigned*)&hi;
        ((uint2*)g_lpack4)[r * LROW + c] = pk;
    }
}

// ---------------- CSR build ----------------
__global__ void k_deg_edges(const int* __restrict__ dst, int e) {
    int i = blockIdx.x * blockDim.x + threadIdx.x;
    if (i < e) atomicAdd(&g_deg[dst[i]], 1);
}

__global__ void k_scan1(int n) {
    __shared__ int ws[SB / 32];
    int tid = threadIdx.x, lane = tid & 31, warp = tid >> 5;
    int i = blockIdx.x * SB + tid;
    int v = (i < n) ? (g_deg[i] + 1) : 0;
#pragma unroll
    for (int o = 16; o > 0; o >>= 1) v += __shfl_xor_sync(0xffffffffu, v, o);
    if (lane == 0) ws[warp] = v;
    __syncthreads();
    if (warp == 0) {
        int s = (lane < SB / 32) ? ws[lane] : 0;
#pragma unroll
        for (int o = 16; o > 0; o >>= 1) s += __shfl_xor_sync(0xffffffffu, s, o);
        if (lane == 0) g_bsum[blockIdx.x] = s;
    }
}

__global__ void k_scan2(int n, int nblk) {
    __shared__ int ws[32];
    int tid = threadIdx.x, lane = tid & 31, warp = tid >> 5;
    int v = (tid < nblk) ? g_bsum[tid] : 0;
    int x = v;
#pragma unroll
    for (int o = 1; o < 32; o <<= 1) {
        int t = __shfl_up_sync(0xffffffffu, x, o);
        if (lane >= o) x += t;
    }
    if (lane == 31) ws[warp] = x;
    __syncthreads();
    if (warp == 0) {
        int y = ws[lane];
#pragma unroll
        for (int o = 1; o < 32; o <<= 1) {
            int t = __shfl_up_sync(0xffffffffu, y, o);
            if (lane >= o) y += t;
        }
        ws[lane] = y;
    }
    __syncthreads();
    int excl = x - v + ((warp == 0) ? 0 : ws[warp - 1]);
    if (tid < nblk) g_bsum[tid] = excl;
    if (tid == nblk - 1) g_rowptr[n] = excl + v;
}

__global__ void k_scan3(const float* __restrict__ sig, int n) {
    __shared__ int ws[SB / 32];
    int tid = threadIdx.x, lane = tid & 31, warp = tid >> 5;
    int i = blockIdx.x * SB + tid;
    int v = (i < n) ? (g_deg[i] + 1) : 0;
    int x = v;
#pragma unroll
    for (int o = 1; o < 32; o <<= 1) {
        int t = __shfl_up_sync(0xffffffffu, x, o);
        if (lane >= o) x += t;
    }
    if (lane == 31) ws[warp] = x;
    __syncthreads();
    if (warp == 0) {
        int y = (lane < SB / 32) ? ws[lane] : 0;
#pragma unroll
        for (int o = 1; o < 32; o <<= 1) {
            int t = __shfl_up_sync(0xffffffffu, y, o);
            if (lane >= o) y += t;
        }
        if (lane < SB / 32) ws[lane] = y;
    }
    __syncthreads();
    int excl = x - v + ((warp == 0) ? 0 : ws[warp - 1]) + g_bsum[blockIdx.x];
    if (i < n) {
        g_rowptr[i] = excl;
        g_col[excl] = i;
        g_cursor[i] = excl + 1;
        float di = rsqrtf((float)v);
        g_dinv[i] = di;
        g_p[i] = di * sig[i];
    }
}

__global__ void k_fill(const int* __restrict__ src, const int* __restrict__ dst, int e) {
    int i = blockIdx.x * blockDim.x + threadIdx.x;
    if (i < e) {
        int p = atomicAdd(&g_cursor[dst[i]], 1);
        g_col[p] = src[i];
    }
}

// ---------------- GCN (rank-1 collapse) ----------------
__global__ void k_gcn_agg(int n) {
    int i = blockIdx.x * blockDim.x + threadIdx.x;
    if (i >= n) return;
    int beg = g_rowptr[i], end = g_rowptr[i + 1];
    float s = 0.f;
    for (int j = beg; j < end; j++) s += g_p[g_col[j]];
    g_sagg[i] = s * g_dinv[i];
}

__global__ void k_gcn_x(const float* __restrict__ w, const float* __restrict__ b, int n) {
    int f = threadIdx.x;
    float wf = w[f], bf = b[f];
    int base = blockIdx.x * 64;
    float s1 = 0.f, s2 = 0.f;
    for (int r = 0; r < 64; r++) {
        int nd = base + r;
        if (nd >= n) break;
        float v = fmaxf(fmaf(g_sagg[nd], wf, bf), 0.f);
        g_x[nd * FF + f] = v;
        s1 += v;
        s2 += v * v;
    }
    atomicAdd(&g_s1[f], s1);
    atomicAdd(&g_s2[f], s2);
}

// ---------------- tensor-core helpers ----------------
__device__ __forceinline__ void mma16816(float c[4], unsigned a0, unsigned a1,
                                         unsigned a2, unsigned a3,
                                         unsigned b0, unsigned b1) {
    asm volatile(
        "mma.sync.aligned.m16n8k16.row.col.f32.f16.f16.f32 "
        "{%0,%1,%2,%3}, {%4,%5,%6,%7}, {%8,%9}, {%0,%1,%2,%3};"
        : "+f"(c[0]), "+f"(c[1]), "+f"(c[2]), "+f"(c[3])
        : "r"(a0), "r"(a1), "r"(a2), "r"(a3), "r"(b0), "r"(b1));
}

__device__ __forceinline__ void ldsm4(unsigned& a0, unsigned& a1, unsigned& a2,
                                      unsigned& a3, unsigned addr) {
    asm volatile("ldmatrix.sync.aligned.m8n8.x4.shared.b16 {%0,%1,%2,%3}, [%4];"
                 : "=r"(a0), "=r"(a1), "=r"(a2), "=r"(a3)
                 : "r"(addr));
}

// ---------------- layer GEMM: h = x @ W, fused GN-apply + attention coefs -----
template <int GN>
__global__ void k_mm(int layer,
                     const float* __restrict__ atts, const float* __restrict__ attd,
                     const float* __restrict__ gnw, const float* __restrict__ gnb,
                     const float* __restrict__ gns, int grp, int n) {
    extern __shared__ char smem[];
    __half* Xs = (__half*)smem;
    __half* Wsh = (__half*)(smem + 128 * XP * 2);
    float* sm_mul = (float*)(smem + 128 * XP * 2 + 33792);
    float* sm_add = sm_mul + FF;
    const uint2* Wp = (const uint2*)Wsh;

    int tid = threadIdx.x;
    int blockRow = blockIdx.x * 128;

    if (GN) {
        if (tid < FF) {
            float invn = 1.0f / (float)n;
            float mu = g_s1[grp * FF + tid] * invn;
            float m2 = g_s2[grp * FF + tid] * invn;
            float mum = gns[tid] * mu;
            float var = m2 - 2.f * mum * mu + mum * mum;
            float inv = rsqrtf(var + 1e-5f);
            float ml = gnw[tid] * inv;
            sm_mul[tid] = ml;
            sm_add[tid] = gnb[tid] - mum * ml;
        }
        __syncthreads();
    }

    {
        const uint4* gw = g_wpack4 + layer * (32 * WROW / 2);
        uint4* ws4 = (uint4*)Wsh;
        for (int i = tid; i < 32 * WROW / 2; i += 256) ws4[i] = gw[i];
    }

    for (int i = tid; i < 128 * 32; i += 256) {
        int row = i >> 5, c4 = i & 31;
        int node = blockRow + row;
        float4 v = make_float4(0.f, 0.f, 0.f, 0.f);
        if (node < n) {
            v = ((const float4*)(g_x + (size_t)node * FF))[c4];
            if (GN) {
                int f = c4 * 4;
                v.x = v.x * sm_mul[f + 0] + sm_add[f + 0];
                v.y = v.y * sm_mul[f + 1] + sm_add[f + 1];
                v.z = v.z * sm_mul[f + 2] + sm_add[f + 2];
                v.w = v.w * sm_mul[f + 3] + sm_add[f + 3];
                ((float4*)(g_x + (size_t)node * FF))[c4] = v;
            }
        }
        __half2 p0 = __floats2half2_rn(v.x, v.y);
        __half2 p1 = __floats2half2_rn(v.z, v.w);
        uint2 pk;
        pk.x = *(unsigned*)&p0;
        pk.y = *(unsigned*)&p1;
        *(uint2*)(Xs + row * XP + c4 * 4) = pk;
    }
    __syncthreads();

    int warp = tid >> 5, lane = tid & 31;
    int warp_m = warp >> 2, warp_n = warp & 3;
    int colbase = warp_n * 32;

    float c[4][4][4];
#pragma unroll
    for (int a = 0; a < 4; a++)
#pragma unroll
        for (int bq = 0; bq < 4; bq++)
#pragma unroll
            for (int d = 0; d < 4; d++) c[a][bq][d] = 0.f;

    unsigned xs_base = (unsigned)__cvta_generic_to_shared(Xs);
    int lrow_add = ((lane >> 3) & 1) * 8 + (lane & 7);
    int lcol_b = (lane >> 4) * 16;

#pragma unroll
    for (int s = 0; s < 8; s++) {
        unsigned a[4][4];
#pragma unroll
        for (int mi = 0; mi < 4; mi++) {
            unsigned addr = xs_base +
                (warp_m * 64 + mi * 16 + lrow_add) * (XP * 2) + s * 32 + lcol_b;
            ldsm4(a[mi][0], a[mi][1], a[mi][2], a[mi][3], addr);
        }
        uint2 bb[4];
#pragma unroll
        for (int ni = 0; ni < 4; ni++)
            bb[ni] = Wp[(s * 4 + (lane & 3)) * WROW + colbase + ni * 8 + (lane >> 2)];
#pragma unroll
        for (int mi = 0; mi < 4; mi++)
#pragma unroll
            for (int ni = 0; ni < 4; ni++)
                mma16816(c[mi][ni], a[mi][0], a[mi][1], a[mi][2], a[mi][3],
                         bb[ni].x, bb[ni].y);
    }

    float2 aS[4], aD[4];
#pragma unroll
    for (int ni = 0; ni < 4; ni++) {
        int c2 = (colbase >> 1) + ni * 4 + (lane & 3);
        aS[ni] = ((const float2*)atts)[c2];
        aD[ni] = ((const float2*)attd)[c2];
    }
    int hd0 = colbase >> 4;

#pragma unroll
    for (int mi = 0; mi < 4; mi++) {
        int grA = blockRow + warp_m * 64 + mi * 16 + (lane >> 2);
        int grB = grA + 8;
        int col0 = colbase + (lane & 3) * 2;
        if (grA < n) {
            __half* hp = g_hh + (size_t)grA * FF + col0;
#pragma unroll
            for (int ni = 0; ni < 4; ni++) {
                __half2 hv = __floats2half2_rn(c[mi][ni][0], c[mi][ni][1]);
                *(__half2*)(hp + ni * 8) = hv;
            }
        }
        if (grB < n) {
            __half* hp = g_hh + (size_t)grB * FF + col0;
#pragma unroll
            for (int ni = 0; ni < 4; ni++) {
                __half2 hv = __floats2half2_rn(c[mi][ni][2], c[mi][ni][3]);
                *(__half2*)(hp + ni * 8) = hv;
            }
        }
        float sAL = c[mi][0][0] * aS[0].x + c[mi][0][1] * aS[0].y +
                    c[mi][1][0] * aS[1].x + c[mi][1][1] * aS[1].y;
        float sAR = c[mi][2][0] * aS[2].x + c[mi][2][1] * aS[2].y +
                    c[mi][3][0] * aS[3].x + c[mi][3][1] * aS[3].y;
        float sBL = c[mi][0][2] * aS[0].x + c[mi][0][3] * aS[0].y +
                    c[mi][1][2] * aS[1].x + c[mi][1][3] * aS[1].y;
        float sBR = c[mi][2][2] * aS[2].x + c[mi][2][3] * aS[2].y +
                    c[mi][3][2] * aS[3].x + c[mi][3][3] * aS[3].y;
        float dAL = c[mi][0][0] * aD[0].x + c[mi][0][1] * aD[0].y +
                    c[mi][1][0] * aD[1].x + c[mi][1][1] * aD[1].y;
        float dAR = c[mi][2][0] * aD[2].x + c[mi][2][1] * aD[2].y +
                    c[mi][3][0] * aD[3].x + c[mi][3][1] * aD[3].y;
        float dBL = c[mi][0][2] * aD[0].x + c[mi][0][3] * aD[0].y +
                    c[mi][1][2] * aD[1].x + c[mi][1][3] * aD[1].y;
        float dBR = c[mi][2][2] * aD[2].x + c[mi][2][3] * aD[2].y +
                    c[mi][3][2] * aD[3].x + c[mi][3][3] * aD[3].y;
#pragma unroll
        for (int o = 1; o < 4; o <<= 1) {
            sAL += __shfl_xor_sync(0xffffffffu, sAL, o);
            sAR += __shfl_xor_sync(0xffffffffu, sAR, o);
            sBL += __shfl_xor_sync(0xffffffffu, sBL, o);
            sBR += __shfl_xor_sync(0xffffffffu, sBR, o);
            dAL += __shfl_xor_sync(0xffffffffu, dAL, o);
            dAR += __shfl_xor_sync(0xffffffffu, dAR, o);
            dBL += __shfl_xor_sync(0xffffffffu, dBL, o);
            dBR += __shfl_xor_sync(0xffffffffu, dBR, o);
        }
        if ((lane & 3) == 0) {
            if (grA < n) {
                g_as[grA * HH + hd0] = sAL;
                g_as[grA * HH + hd0 + 1] = sAR;
                g_ad[grA * HH + hd0] = dAL;
                g_ad[grA * HH + hd0 + 1] = dAR;
            }
            if (grB < n) {
                g_as[grB * HH + hd0] = sBL;
                g_as[grB * HH + hd0 + 1] = sBR;
                g_ad[grB * HH + hd0] = dBL;
                g_ad[grB * HH + hd0 + 1] = dBR;
            }
        }
    }
}

// ---------------- output projection (reads fp16 x packed into g_x rows) ------
__global__ void k_lin(const float* __restrict__ b, float* __restrict__ out, int n) {
    extern __shared__ char smem[];
    __half* Xs = (__half*)smem;
    __half* Wsh = (__half*)(smem + 128 * XP * 2);
    const uint2* Wp = (const uint2*)Wsh;
    int tid = threadIdx.x;
    int blockRow = blockIdx.x * 128;

    {
        uint4* ws4 = (uint4*)Wsh;
        for (int i = tid; i < 32 * LROW / 2; i += 256) ws4[i] = g_lpack4[i];
    }

    for (int i = tid; i < 128 * 16; i += 256) {
        int row = i >> 4, c8 = i & 15;
        int node = blockRow + row;
        uint4 pk = make_uint4(0u, 0u, 0u, 0u);
        if (node < n)
            pk = *(const uint4*)((const __half*)(g_x + (size_t)node * FF) + c8 * 8);
        *(uint4*)(Xs + row * XP + c8 * 8) = pk;
    }
    __syncthreads();

    int warp = tid >> 5, lane = tid & 31;
    int warp_m = warp >> 1, warp_n = warp & 1;
    int colbase = warp_n * 32;

    float c[2][4][4];
#pragma unroll
    for (int a = 0; a < 2; a++)
#pragma unroll
        for (int bq = 0; bq < 4; bq++)
#pragma unroll
            for (int d = 0; d < 4; d++) c[a][bq][d] = 0.f;

    unsigned xs_base = (unsigned)__cvta_generic_to_shared(Xs);
    int lrow_add = ((lane >> 3) & 1) * 8 + (lane & 7);
    int lcol_b = (lane >> 4) * 16;

#pragma unroll
    for (int s = 0; s < 8; s++) {
        unsigned a[2][4];
#pragma unroll
        for (int mi = 0; mi < 2; mi++) {
            unsigned addr = xs_base +
                (warp_m * 32 + mi * 16 + lrow_add) * (XP * 2) + s * 32 + lcol_b;
            ldsm4(a[mi][0], a[mi][1], a[mi][2], a[mi][3], addr);
        }
        uint2 bb[4];
#pragma unroll
        for (int ni = 0; ni < 4; ni++)
            bb[ni] = Wp[(s * 4 + (lane & 3)) * LROW + colbase + ni * 8 + (lane >> 2)];
#pragma unroll
        for (int mi = 0; mi < 2; mi++)
#pragma unroll
            for (int ni = 0; ni < 4; ni++)
                mma16816(c[mi][ni], a[mi][0], a[mi][1], a[mi][2], a[mi][3],
                         bb[ni].x, bb[ni].y);
    }

#pragma unroll
    for (int mi = 0; mi < 2; mi++) {
        int grA = blockRow + warp_m * 32 + mi * 16 + (lane >> 2);
        int grB = grA + 8;
        int col0 = colbase + (lane & 3) * 2;
#pragma unroll
        for (int ni = 0; ni < 4; ni++) {
            float2 bv = ((const float2*)b)[(col0 + ni * 8) >> 1];
            if (grA < n) {
                float2 o = make_float2(c[mi][ni][0] + bv.x, c[mi][ni][1] + bv.y);
                *(float2*)(out + (size_t)grA * 64 + col0 + ni * 8) = o;
            }
            if (grB < n) {
                float2 o = make_float2(c[mi][ni][2] + bv.x, c[mi][ni][3] + bv.y);
                *(float2*)(out + (size_t)grB * 64 + col0 + ni * 8) = o;
            }
        }
    }
}

// ---------------- edge softmax + aggregation + residual ----------------------
// FIN: last layer — store updated x as fp16 packed into the node's own g_x
// row (identical __floats2half2_rn rounding k_lin would apply anyway; each
// row is written only by its owning warp, read only by k_lin afterward).
template <int STATS, int FIN>
__global__ void k_attn(const float* __restrict__ gb, int n) {
    __shared__ float bsum[FF];
    __shared__ float bsq[FF];
    int tid = threadIdx.x;
    int warp = tid >> 5, lane = tid & 31;
    int node = blockIdx.x * 8 + warp;

    if (STATS) {
        if (tid < FF) { bsum[tid] = 0.f; bsq[tid] = 0.f; }
        __syncthreads();
    }

    int half = lane >> 4, fl = lane & 15;
    int hd = fl >> 1;
    int f0 = fl * 8 + half * 4;

    float4 xv = {0, 0, 0, 0};
    if (node < n) {
        int beg = g_rowptr[node], end = g_rowptr[node + 1];
        float adh = g_ad[node * HH + hd];

        float s = 0.f;
        float acc[8] = {0.f, 0.f, 0.f, 0.f, 0.f, 0.f, 0.f, 0.f};
        for (int jb = beg; jb < end; jb += 2) {
            int j = jb + half;
            bool valid = (j < end);
            int u = valid ? g_col[j] : node;
            float ev = g_as[u * HH + hd] + adh;
            ev = ev > 0.f ? ev : 0.2f * ev;
            float w = valid ? __expf(ev) : 0.f;
            float4 hv4 = *(const float4*)(g_hh + (size_t)u * FF + fl * 8);
            const __half2* hp = (const __half2*)&hv4;
            s += w;
#pragma unroll
            for (int q = 0; q < 4; q++) {
                float2 f = __half22float2(hp[q]);
                acc[2 * q + 0] += w * f.x;
                acc[2 * q + 1] += w * f.y;
            }
        }

        s += __shfl_xor_sync(0xffffffffu, s, 16);
#pragma unroll
        for (int q = 0; q < 8; q++)
            acc[q] += __shfl_xor_sync(0xffffffffu, acc[q], 16);
        float rd = 1.0f / s;

        float4 b4 = *(const float4*)(gb + f0);
        float* xp = g_x + (size_t)node * FF + f0;
        xv = *(float4*)xp;
        int o = half * 4;
        xv.x += fmaxf(acc[o + 0] * rd + b4.x, 0.f);
        xv.y += fmaxf(acc[o + 1] * rd + b4.y, 0.f);
        xv.z += fmaxf(acc[o + 2] * rd + b4.z, 0.f);
        xv.w += fmaxf(acc[o + 3] * rd + b4.w, 0.f);
        if (FIN) {
            // pack fp16 into the node's own row (first 256 B); k_lin reads this
            uint2 pk;
            ((__half2*)&pk)[0] = __floats2half2_rn(xv.x, xv.y);
            ((__half2*)&pk)[1] = __floats2half2_rn(xv.z, xv.w);
            *(uint2*)((__half*)(g_x + (size_t)node * FF) + f0) = pk;
        } else {
            *(float4*)xp = xv;
        }
    }

    if (STATS) {
        if (node < n) {
            atomicAdd(&bsum[f0 + 0], xv.x); atomicAdd(&bsq[f0 + 0], xv.x * xv.x);
            atomicAdd(&bsum[f0 + 1], xv.y); atomicAdd(&bsq[f0 + 1], xv.y * xv.y);
            atomicAdd(&bsum[f0 + 2], xv.z); atomicAdd(&bsq[f0 + 2], xv.z * xv.z);
            atomicAdd(&bsum[f0 + 3], xv.w); atomicAdd(&bsq[f0 + 3], xv.w * xv.w);
        }
        __syncthreads();
        if (tid < FF) {
            atomicAdd(&g_s1[FF + tid], bsum[tid]);
            atomicAdd(&g_s2[FF + tid], bsq[tid]);
        }
    }
}

// ---------------- launch ----------------
extern "C" void kernel_launch(void* const* d_in, const int* in_sizes, int n_in,
                              void* d_out, int out_size) {
    const float* signals = (const float*)d_in[0];
    const int*   ei      = (const int*)d_in[1];
    const float* gcn_w   = (const float*)d_in[2];
    const float* gcn_b   = (const float*)d_in[3];
    const float* gat_w   = (const float*)d_in[4];
    const float* att_src = (const float*)d_in[5];
    const float* att_dst = (const float*)d_in[6];
    const float* gat_b   = (const float*)d_in[7];
    const float* gn_w    = (const float*)d_in[8];
    const float* gn_b    = (const float*)d_in[9];
    const float* gn_s    = (const float*)d_in[10];
    const float* lin_w   = (const float*)d_in[11];
    const float* lin_b   = (const float*)d_in[12];

    int n = in_sizes[0];
    int e = in_sizes[1] / 2;
    const int* src = ei;
    const int* dst = ei + e;

    const int MM_SMEM = 128 * XP * 2 + 33792 + 2 * FF * 4;  // 69632
    const int LIN_SMEM = 128 * XP * 2 + 17408;              // 52224
    cudaFuncSetAttribute(k_mm<0>, cudaFuncAttributeMaxDynamicSharedMemorySize, MM_SMEM);
    cudaFuncSetAttribute(k_mm<1>, cudaFuncAttributeMaxDynamicSharedMemorySize, MM_SMEM);
    cudaFuncSetAttribute(k_lin, cudaFuncAttributeMaxDynamicSharedMemorySize, LIN_SMEM);

    const int B = 256;
    int nblk = (n + SB - 1) / SB;
    int wz_grid = (n + B - 1) / B;
    k_wpack<<<wz_grid, B>>>(gat_w, lin_w, n);
    k_deg_edges<<<(e + B - 1) / B, B>>>(dst, e);
    k_scan1<<<nblk, SB>>>(n);
    k_scan2<<<1, 1024>>>(n, nblk);
    k_scan3<<<nblk, SB>>>(signals, n);
    k_fill<<<(e + B - 1) / B, B>>>(src, dst, e);

    k_gcn_agg<<<(n + B - 1) / B, B>>>(n);
    k_gcn_x<<<(n + 63) / 64, 128>>>(gcn_w, gcn_b, n);  // + GN group-0 stats

    int grid_mm = (n + 127) / 128;
    int grid_at = (n + 7) / 8;
    for (int i = 0; i < NLAY; i++) {
        const float* aS = att_src + i * HH * CC;
        const float* aD = att_dst + i * HH * CC;
        if (i % GNFREQ == 0) {
            int g = i / GNFREQ;
            k_mm<1><<<grid_mm, 256, MM_SMEM>>>(i, aS, aD, gn_w + g * FF,
                                               gn_b + g * FF, gn_s + g * FF, g, n);
        } else {
            k_mm<0><<<grid_mm, 256, MM_SMEM>>>(i, aS, aD, nullptr, nullptr, nullptr, 0, n);
        }
        const float* gb = gat_b + i * FF;
        if (i == 2) {
            k_attn<1, 0><<<grid_at, 256>>>(gb, n);  // + GN group-1 stats
        } else if (i == NLAY - 1) {
            k_attn<0, 1><<<grid_at, 256>>>(gb, n);  // final: fp16 pack for k_lin
        } else {
            k_attn<0, 0><<<grid_at, 256>>>(gb, n);
        }
    }

    k_lin<<<grid_mm, 256, LIN_SMEM>>>(lin_b, (float*)d_out, n);
}

// round 17
// speedup vs baseline: 1.0401x; 1.0182x over previous
#include <cuda_runtime.h>
#include <cuda_fp16.h>
#include <cstdint>
#include <cstddef>
#include <math.h>

#define NN 50000
#define EE 800000
#define FF 128
#define HH 8
#define CC 16
#define NLAY 5
#define GNFREQ 3
#define ETOT (EE + NN)

#define XP 136
#define WROW 132
#define LROW 68
#define SB 512
#define NSCANB ((NN + SB - 1) / SB)

// ---------------- device scratch ----------------
__device__ float  g_x[NN * FF];      // fp32 residual stream; fp16-packed from layer-3 attn onward
__device__ __half g_hh[NN * FF];
__device__ float  g_as[NN * HH];
__device__ float  g_ad[NN * HH];
__device__ float  g_sagg[NN];
__device__ float  g_dinv[NN];
__device__ float  g_p[NN];
__device__ int    g_rowptr[NN + 1];
__device__ int    g_deg[NN];
__device__ int    g_cursor[NN];
__device__ int    g_col[ETOT];
__device__ float  g_s1[2 * FF];
__device__ float  g_s2[2 * FF];
__device__ int    g_bsum[NSCANB + 1];
__device__ uint4  g_wpack4[NLAY * 32 * WROW / 2];
__device__ uint4  g_lpack4[32 * LROW / 2];

// ---------------- weight pre-pack + scratch zero (merged) ----------------
__global__ void k_wpack(const float* __restrict__ gat_w, const float* __restrict__ lin_w,
                        int n) {
    int i = blockIdx.x * blockDim.x + threadIdx.x;
    if (i < n) g_deg[i] = 0;
    if (i < 2 * FF) { g_s1[i] = 0.f; g_s2[i] = 0.f; }
    if (i < NLAY * 32 * 128) {
        int l = i / (32 * 128);
        int r = (i / 128) & 31;
        int c = i & 127;
        int k0 = 16 * (r >> 2) + 2 * (r & 3);
        const float* W = gat_w + (size_t)l * FF * FF;
        __half2 lo = __floats2half2_rn(W[k0 * FF + c], W[(k0 + 1) * FF + c]);
        __half2 hi = __floats2half2_rn(W[(k0 + 8) * FF + c], W[(k0 + 9) * FF + c]);
        uint2 pk;
        pk.x = *(unsigned*)&lo;
        pk.y = *(unsigned*)&hi;
        ((uint2*)g_wpack4)[l * 32 * WROW + r * WROW + c] = pk;
    } else if (i < NLAY * 32 * 128 + 32 * 64) {
        int i2 = i - NLAY * 32 * 128;
        int r = i2 >> 6, c = i2 & 63;
        int k0 = 16 * (r >> 2) + 2 * (r & 3);
        __half2 lo = __floats2half2_rn(lin_w[k0 * 64 + c], lin_w[(k0 + 1) * 64 + c]);
        __half2 hi = __floats2half2_rn(lin_w[(k0 + 8) * 64 + c], lin_w[(k0 + 9) * 64 + c]);
        uint2 pk;
        pk.x = *(unsigned*)&lo;
        pk.y = *(unsigned*)&hi;
        ((uint2*)g_lpack4)[r * LROW + c] = pk;
    }
}

// ---------------- CSR build ----------------
__global__ void k_deg_edges(const int* __restrict__ dst, int e) {
    int i = blockIdx.x * blockDim.x + threadIdx.x;
    if (i < e) atomicAdd(&g_deg[dst[i]], 1);
}

__global__ void k_scan1(int n) {
    __shared__ int ws[SB / 32];
    int tid = threadIdx.x, lane = tid & 31, warp = tid >> 5;
    int i = blockIdx.x * SB + tid;
    int v = (i < n) ? (g_deg[i] + 1) : 0;
#pragma unroll
    for (int o = 16; o > 0; o >>= 1) v += __shfl_xor_sync(0xffffffffu, v, o);
    if (lane == 0) ws[warp] = v;
    __syncthreads();
    if (warp == 0) {
        int s = (lane < SB / 32) ? ws[lane] : 0;
#pragma unroll
        for (int o = 16; o > 0; o >>= 1) s += __shfl_xor_sync(0xffffffffu, s, o);
        if (lane == 0) g_bsum[blockIdx.x] = s;
    }
}

__global__ void k_scan2(int n, int nblk) {
    __shared__ int ws[32];
    int tid = threadIdx.x, lane = tid & 31, warp = tid >> 5;
    int v = (tid < nblk) ? g_bsum[tid] : 0;
    int x = v;
#pragma unroll
    for (int o = 1; o < 32; o <<= 1) {
        int t = __shfl_up_sync(0xffffffffu, x, o);
        if (lane >= o) x += t;
    }
    if (lane == 31) ws[warp] = x;
    __syncthreads();
    if (warp == 0) {
        int y = ws[lane];
#pragma unroll
        for (int o = 1; o < 32; o <<= 1) {
            int t = __shfl_up_sync(0xffffffffu, y, o);
            if (lane >= o) y += t;
        }
        ws[lane] = y;
    }
    __syncthreads();
    int excl = x - v + ((warp == 0) ? 0 : ws[warp - 1]);
    if (tid < nblk) g_bsum[tid] = excl;
    if (tid == nblk - 1) g_rowptr[n] = excl + v;
}

__global__ void k_scan3(const float* __restrict__ sig, int n) {
    __shared__ int ws[SB / 32];
    int tid = threadIdx.x, lane = tid & 31, warp = tid >> 5;
    int i = blockIdx.x * SB + tid;
    int v = (i < n) ? (g_deg[i] + 1) : 0;
    int x = v;
#pragma unroll
    for (int o = 1; o < 32; o <<= 1) {
        int t = __shfl_up_sync(0xffffffffu, x, o);
        if (lane >= o) x += t;
    }
    if (lane == 31) ws[warp] = x;
    __syncthreads();
    if (warp == 0) {
        int y = (lane < SB / 32) ? ws[lane] : 0;
#pragma unroll
        for (int o = 1; o < 32; o <<= 1) {
            int t = __shfl_up_sync(0xffffffffu, y, o);
            if (lane >= o) y += t;
        }
        if (lane < SB / 32) ws[lane] = y;
    }
    __syncthreads();
    int excl = x - v + ((warp == 0) ? 0 : ws[warp - 1]) + g_bsum[blockIdx.x];
    if (i < n) {
        g_rowptr[i] = excl;
        g_col[excl] = i;
        g_cursor[i] = excl + 1;
        float di = rsqrtf((float)v);
        g_dinv[i] = di;
        g_p[i] = di * sig[i];
    }
}

__global__ void k_fill(const int* __restrict__ src, const int* __restrict__ dst, int e) {
    int i = blockIdx.x * blockDim.x + threadIdx.x;
    if (i < e) {
        int p = atomicAdd(&g_cursor[dst[i]], 1);
        g_col[p] = src[i];
    }
}

// ---------------- GCN (rank-1 collapse) ----------------
__global__ void k_gcn_agg(int n) {
    int i = blockIdx.x * blockDim.x + threadIdx.x;
    if (i >= n) return;
    int beg = g_rowptr[i], end = g_rowptr[i + 1];
    float s = 0.f;
    for (int j = beg; j < end; j++) s += g_p[g_col[j]];
    g_sagg[i] = s * g_dinv[i];
}

__global__ void k_gcn_x(const float* __restrict__ w, const float* __restrict__ b, int n) {
    int f = threadIdx.x;
    float wf = w[f], bf = b[f];
    int base = blockIdx.x * 64;
    float s1 = 0.f, s2 = 0.f;
    for (int r = 0; r < 64; r++) {
        int nd = base + r;
        if (nd >= n) break;
        float v = fmaxf(fmaf(g_sagg[nd], wf, bf), 0.f);
        g_x[nd * FF + f] = v;
        s1 += v;
        s2 += v * v;
    }
    atomicAdd(&g_s1[f], s1);
    atomicAdd(&g_s2[f], s2);
}

// ---------------- tensor-core helpers ----------------
__device__ __forceinline__ void mma16816(float c[4], unsigned a0, unsigned a1,
                                         unsigned a2, unsigned a3,
                                         unsigned b0, unsigned b1) {
    asm volatile(
        "mma.sync.aligned.m16n8k16.row.col.f32.f16.f16.f32 "
        "{%0,%1,%2,%3}, {%4,%5,%6,%7}, {%8,%9}, {%0,%1,%2,%3};"
        : "+f"(c[0]), "+f"(c[1]), "+f"(c[2]), "+f"(c[3])
        : "r"(a0), "r"(a1), "r"(a2), "r"(a3), "r"(b0), "r"(b1));
}

__device__ __forceinline__ void ldsm4(unsigned& a0, unsigned& a1, unsigned& a2,
                                      unsigned& a3, unsigned addr) {
    asm volatile("ldmatrix.sync.aligned.m8n8.x4.shared.b16 {%0,%1,%2,%3}, [%4];"
                 : "=r"(a0), "=r"(a1), "=r"(a2), "=r"(a3)
                 : "r"(addr));
}

// ---------------- layer GEMM: h = x @ W, fused GN-apply + attention coefs -----
// XH: x rows hold fp16 packed in first 256 B (written by a FINW attn layer).
template <int GN, int XH>
__global__ void k_mm(int layer,
                     const float* __restrict__ atts, const float* __restrict__ attd,
                     const float* __restrict__ gnw, const float* __restrict__ gnb,
                     const float* __restrict__ gns, int grp, int n) {
    extern __shared__ char smem[];
    __half* Xs = (__half*)smem;
    __half* Wsh = (__half*)(smem + 128 * XP * 2);
    float* sm_mul = (float*)(smem + 128 * XP * 2 + 33792);
    float* sm_add = sm_mul + FF;
    const uint2* Wp = (const uint2*)Wsh;

    int tid = threadIdx.x;
    int blockRow = blockIdx.x * 128;

    if (GN) {
        if (tid < FF) {
            float invn = 1.0f / (float)n;
            float mu = g_s1[grp * FF + tid] * invn;
            float m2 = g_s2[grp * FF + tid] * invn;
            float mum = gns[tid] * mu;
            float var = m2 - 2.f * mum * mu + mum * mum;
            float inv = rsqrtf(var + 1e-5f);
            float ml = gnw[tid] * inv;
            sm_mul[tid] = ml;
            sm_add[tid] = gnb[tid] - mum * ml;
        }
        __syncthreads();
    }

    {
        const uint4* gw = g_wpack4 + layer * (32 * WROW / 2);
        uint4* ws4 = (uint4*)Wsh;
        for (int i = tid; i < 32 * WROW / 2; i += 256) ws4[i] = gw[i];
    }

    if (XH) {
        for (int i = tid; i < 128 * 16; i += 256) {
            int row = i >> 4, c8 = i & 15;
            int node = blockRow + row;
            uint4 pk = make_uint4(0u, 0u, 0u, 0u);
            if (node < n)
                pk = *(const uint4*)((const __half*)(g_x + (size_t)node * FF) + c8 * 8);
            *(uint4*)(Xs + row * XP + c8 * 8) = pk;
        }
    } else {
        for (int i = tid; i < 128 * 32; i += 256) {
            int row = i >> 5, c4 = i & 31;
            int node = blockRow + row;
            float4 v = make_float4(0.f, 0.f, 0.f, 0.f);
            if (node < n) {
                v = ((const float4*)(g_x + (size_t)node * FF))[c4];
                if (GN) {
                    int f = c4 * 4;
                    v.x = v.x * sm_mul[f + 0] + sm_add[f + 0];
                    v.y = v.y * sm_mul[f + 1] + sm_add[f + 1];
                    v.z = v.z * sm_mul[f + 2] + sm_add[f + 2];
                    v.w = v.w * sm_mul[f + 3] + sm_add[f + 3];
                    ((float4*)(g_x + (size_t)node * FF))[c4] = v;
                }
            }
            __half2 p0 = __floats2half2_rn(v.x, v.y);
            __half2 p1 = __floats2half2_rn(v.z, v.w);
            uint2 pk;
            pk.x = *(unsigned*)&p0;
            pk.y = *(unsigned*)&p1;
            *(uint2*)(Xs + row * XP + c4 * 4) = pk;
        }
    }
    __syncthreads();

    int warp = tid >> 5, lane = tid & 31;
    int warp_m = warp >> 2, warp_n = warp & 3;
    int colbase = warp_n * 32;

    float c[4][4][4];
#pragma unroll
    for (int a = 0; a < 4; a++)
#pragma unroll
        for (int bq = 0; bq < 4; bq++)
#pragma unroll
            for (int d = 0; d < 4; d++) c[a][bq][d] = 0.f;

    unsigned xs_base = (unsigned)__cvta_generic_to_shared(Xs);
    int lrow_add = ((lane >> 3) & 1) * 8 + (lane & 7);
    int lcol_b = (lane >> 4) * 16;

#pragma unroll
    for (int s = 0; s < 8; s++) {
        unsigned a[4][4];
#pragma unroll
        for (int mi = 0; mi < 4; mi++) {
            unsigned addr = xs_base +
                (warp_m * 64 + mi * 16 + lrow_add) * (XP * 2) + s * 32 + lcol_b;
            ldsm4(a[mi][0], a[mi][1], a[mi][2], a[mi][3], addr);
        }
        uint2 bb[4];
#pragma unroll
        for (int ni = 0; ni < 4; ni++)
            bb[ni] = Wp[(s * 4 + (lane & 3)) * WROW + colbase + ni * 8 + (lane >> 2)];
#pragma unroll
        for (int mi = 0; mi < 4; mi++)
#pragma unroll
            for (int ni = 0; ni < 4; ni++)
                mma16816(c[mi][ni], a[mi][0], a[mi][1], a[mi][2], a[mi][3],
                         bb[ni].x, bb[ni].y);
    }

    float2 aS[4], aD[4];
#pragma unroll
    for (int ni = 0; ni < 4; ni++) {
        int c2 = (colbase >> 1) + ni * 4 + (lane & 3);
        aS[ni] = ((const float2*)atts)[c2];
        aD[ni] = ((const float2*)attd)[c2];
    }
    int hd0 = colbase >> 4;

#pragma unroll
    for (int mi = 0; mi < 4; mi++) {
        int grA = blockRow + warp_m * 64 + mi * 16 + (lane >> 2);
        int grB = grA + 8;
        int col0 = colbase + (lane & 3) * 2;
        if (grA < n) {
            __half* hp = g_hh + (size_t)grA * FF + col0;
#pragma unroll
            for (int ni = 0; ni < 4; ni++) {
                __half2 hv = __floats2half2_rn(c[mi][ni][0], c[mi][ni][1]);
                *(__half2*)(hp + ni * 8) = hv;
            }
        }
        if (grB < n) {
            __half* hp = g_hh + (size_t)grB * FF + col0;
#pragma unroll
            for (int ni = 0; ni < 4; ni++) {
                __half2 hv = __floats2half2_rn(c[mi][ni][2], c[mi][ni][3]);
                *(__half2*)(hp + ni * 8) = hv;
            }
        }
        float sAL = c[mi][0][0] * aS[0].x + c[mi][0][1] * aS[0].y +
                    c[mi][1][0] * aS[1].x + c[mi][1][1] * aS[1].y;
        float sAR = c[mi][2][0] * aS[2].x + c[mi][2][1] * aS[2].y +
                    c[mi][3][0] * aS[3].x + c[mi][3][1] * aS[3].y;
        float sBL = c[mi][0][2] * aS[0].x + c[mi][0][3] * aS[0].y +
                    c[mi][1][2] * aS[1].x + c[mi][1][3] * aS[1].y;
        float sBR = c[mi][2][2] * aS[2].x + c[mi][2][3] * aS[2].y +
                    c[mi][3][2] * aS[3].x + c[mi][3][3] * aS[3].y;
        float dAL = c[mi][0][0] * aD[0].x + c[mi][0][1] * aD[0].y +
                    c[mi][1][0] * aD[1].x + c[mi][1][1] * aD[1].y;
        float dAR = c[mi][2][0] * aD[2].x + c[mi][2][1] * aD[2].y +
                    c[mi][3][0] * aD[3].x + c[mi][3][1] * aD[3].y;
        float dBL = c[mi][0][2] * aD[0].x + c[mi][0][3] * aD[0].y +
                    c[mi][1][2] * aD[1].x + c[mi][1][3] * aD[1].y;
        float dBR = c[mi][2][2] * aD[2].x + c[mi][2][3] * aD[2].y +
                    c[mi][3][2] * aD[3].x + c[mi][3][3] * aD[3].y;
#pragma unroll
        for (int o = 1; o < 4; o <<= 1) {
            sAL += __shfl_xor_sync(0xffffffffu, sAL, o);
            sAR += __shfl_xor_sync(0xffffffffu, sAR, o);
            sBL += __shfl_xor_sync(0xffffffffu, sBL, o);
            sBR += __shfl_xor_sync(0xffffffffu, sBR, o);
            dAL += __shfl_xor_sync(0xffffffffu, dAL, o);
            dAR += __shfl_xor_sync(0xffffffffu, dAR, o);
            dBL += __shfl_xor_sync(0xffffffffu, dBL, o);
            dBR += __shfl_xor_sync(0xffffffffu, dBR, o);
        }
        if ((lane & 3) == 0) {
            if (grA < n) {
                g_as[grA * HH + hd0] = sAL;
                g_as[grA * HH + hd0 + 1] = sAR;
                g_ad[grA * HH + hd0] = dAL;
                g_ad[grA * HH + hd0 + 1] = dAR;
            }
            if (grB < n) {
                g_as[grB * HH + hd0] = sBL;
                g_as[grB * HH + hd0 + 1] = sBR;
                g_ad[grB * HH + hd0] = dBL;
                g_ad[grB * HH + hd0 + 1] = dBR;
            }
        }
    }
}

// ---------------- output projection (reads fp16 x packed into g_x rows) ------
__global__ void k_lin(const float* __restrict__ b, float* __restrict__ out, int n) {
    extern __shared__ char smem[];
    __half* Xs = (__half*)smem;
    __half* Wsh = (__half*)(smem + 128 * XP * 2);
    const uint2* Wp = (const uint2*)Wsh;
    int tid = threadIdx.x;
    int blockRow = blockIdx.x * 128;

    {
        uint4* ws4 = (uint4*)Wsh;
        for (int i = tid; i < 32 * LROW / 2; i += 256) ws4[i] = g_lpack4[i];
    }

    for (int i = tid; i < 128 * 16; i += 256) {
        int row = i >> 4, c8 = i & 15;
        int node = blockRow + row;
        uint4 pk = make_uint4(0u, 0u, 0u, 0u);
        if (node < n)
            pk = *(const uint4*)((const __half*)(g_x + (size_t)node * FF) + c8 * 8);
        *(uint4*)(Xs + row * XP + c8 * 8) = pk;
    }
    __syncthreads();

    int warp = tid >> 5, lane = tid & 31;
    int warp_m = warp >> 1, warp_n = warp & 1;
    int colbase = warp_n * 32;

    float c[2][4][4];
#pragma unroll
    for (int a = 0; a < 2; a++)
#pragma unroll
        for (int bq = 0; bq < 4; bq++)
#pragma unroll
            for (int d = 0; d < 4; d++) c[a][bq][d] = 0.f;

    unsigned xs_base = (unsigned)__cvta_generic_to_shared(Xs);
    int lrow_add = ((lane >> 3) & 1) * 8 + (lane & 7);
    int lcol_b = (lane >> 4) * 16;

#pragma unroll
    for (int s = 0; s < 8; s++) {
        unsigned a[2][4];
#pragma unroll
        for (int mi = 0; mi < 2; mi++) {
            unsigned addr = xs_base +
                (warp_m * 32 + mi * 16 + lrow_add) * (XP * 2) + s * 32 + lcol_b;
            ldsm4(a[mi][0], a[mi][1], a[mi][2], a[mi][3], addr);
        }
        uint2 bb[4];
#pragma unroll
        for (int ni = 0; ni < 4; ni++)
            bb[ni] = Wp[(s * 4 + (lane & 3)) * LROW + colbase + ni * 8 + (lane >> 2)];
#pragma unroll
        for (int mi = 0; mi < 2; mi++)
#pragma unroll
            for (int ni = 0; ni < 4; ni++)
                mma16816(c[mi][ni], a[mi][0], a[mi][1], a[mi][2], a[mi][3],
                         bb[ni].x, bb[ni].y);
    }

#pragma unroll
    for (int mi = 0; mi < 2; mi++) {
        int grA = blockRow + warp_m * 32 + mi * 16 + (lane >> 2);
        int grB = grA + 8;
        int col0 = colbase + (lane & 3) * 2;
#pragma unroll
        for (int ni = 0; ni < 4; ni++) {
            float2 bv = ((const float2*)b)[(col0 + ni * 8) >> 1];
            if (grA < n) {
                float2 o = make_float2(c[mi][ni][0] + bv.x, c[mi][ni][1] + bv.y);
                *(float2*)(out + (size_t)grA * 64 + col0 + ni * 8) = o;
            }
            if (grB < n) {
                float2 o = make_float2(c[mi][ni][2] + bv.x, c[mi][ni][3] + bv.y);
                *(float2*)(out + (size_t)grB * 64 + col0 + ni * 8) = o;
            }
        }
    }
}

// ---------------- edge softmax + aggregation + residual ----------------------
// FINW: store updated x fp16-packed into the node's own row.
// FINR: residual x is already fp16-packed (read that format).
template <int STATS, int FINW, int FINR>
__global__ void k_attn(const float* __restrict__ gb, int n) {
    __shared__ float bsum[FF];
    __shared__ float bsq[FF];
    int tid = threadIdx.x;
    int warp = tid >> 5, lane = tid & 31;
    int node = blockIdx.x * 8 + warp;

    if (STATS) {
        if (tid < FF) { bsum[tid] = 0.f; bsq[tid] = 0.f; }
        __syncthreads();
    }

    int half = lane >> 4, fl = lane & 15;
    int hd = fl >> 1;
    int f0 = fl * 8 + half * 4;

    float4 xv = {0, 0, 0, 0};
    if (node < n) {
        int beg = g_rowptr[node], end = g_rowptr[node + 1];
        float adh = g_ad[node * HH + hd];

        float s = 0.f;
        float acc[8] = {0.f, 0.f, 0.f, 0.f, 0.f, 0.f, 0.f, 0.f};
        for (int jb = beg; jb < end; jb += 2) {
            int j = jb + half;
            bool valid = (j < end);
            int u = valid ? g_col[j] : node;
            float ev = g_as[u * HH + hd] + adh;
            ev = ev > 0.f ? ev : 0.2f * ev;
            float w = valid ? __expf(ev) : 0.f;
            float4 hv4 = *(const float4*)(g_hh + (size_t)u * FF + fl * 8);
            const __half2* hp = (const __half2*)&hv4;
            s += w;
#pragma unroll
            for (int q = 0; q < 4; q++) {
                float2 f = __half22float2(hp[q]);
                acc[2 * q + 0] += w * f.x;
                acc[2 * q + 1] += w * f.y;
            }
        }

        s += __shfl_xor_sync(0xffffffffu, s, 16);
#pragma unroll
        for (int q = 0; q < 8; q++)
            acc[q] += __shfl_xor_sync(0xffffffffu, acc[q], 16);
        float rd = 1.0f / s;

        float4 b4 = *(const float4*)(gb + f0);
        float* xp = g_x + (size_t)node * FF + f0;
        if (FINR) {
            uint2 xpk = *(uint2*)((__half*)(g_x + (size_t)node * FF) + f0);
            float2 xa = __half22float2(((__half2*)&xpk)[0]);
            float2 xb = __half22float2(((__half2*)&xpk)[1]);
            xv = make_float4(xa.x, xa.y, xb.x, xb.y);
        } else {
            xv = *(float4*)xp;
        }
        int o = half * 4;
        xv.x += fmaxf(acc[o + 0] * rd + b4.x, 0.f);
        xv.y += fmaxf(acc[o + 1] * rd + b4.y, 0.f);
        xv.z += fmaxf(acc[o + 2] * rd + b4.z, 0.f);
        xv.w += fmaxf(acc[o + 3] * rd + b4.w, 0.f);
        if (FINW) {
            uint2 pk;
            ((__half2*)&pk)[0] = __floats2half2_rn(xv.x, xv.y);
            ((__half2*)&pk)[1] = __floats2half2_rn(xv.z, xv.w);
            *(uint2*)((__half*)(g_x + (size_t)node * FF) + f0) = pk;
        } else {
            *(float4*)xp = xv;
        }
    }

    if (STATS) {
        if (node < n) {
            atomicAdd(&bsum[f0 + 0], xv.x); atomicAdd(&bsq[f0 + 0], xv.x * xv.x);
            atomicAdd(&bsum[f0 + 1], xv.y); atomicAdd(&bsq[f0 + 1], xv.y * xv.y);
            atomicAdd(&bsum[f0 + 2], xv.z); atomicAdd(&bsq[f0 + 2], xv.z * xv.z);
            atomicAdd(&bsum[f0 + 3], xv.w); atomicAdd(&bsq[f0 + 3], xv.w * xv.w);
        }
        __syncthreads();
        if (tid < FF) {
            atomicAdd(&g_s1[FF + tid], bsum[tid]);
            atomicAdd(&g_s2[FF + tid], bsq[tid]);
        }
    }
}

// ---------------- launch ----------------
extern "C" void kernel_launch(void* const* d_in, const int* in_sizes, int n_in,
                              void* d_out, int out_size) {
    const float* signals = (const float*)d_in[0];
    const int*   ei      = (const int*)d_in[1];
    const float* gcn_w   = (const float*)d_in[2];
    const float* gcn_b   = (const float*)d_in[3];
    const float* gat_w   = (const float*)d_in[4];
    const float* att_src = (const float*)d_in[5];
    const float* att_dst = (const float*)d_in[6];
    const float* gat_b   = (const float*)d_in[7];
    const float* gn_w    = (const float*)d_in[8];
    const float* gn_b    = (const float*)d_in[9];
    const float* gn_s    = (const float*)d_in[10];
    const float* lin_w   = (const float*)d_in[11];
    const float* lin_b   = (const float*)d_in[12];

    int n = in_sizes[0];
    int e = in_sizes[1] / 2;
    const int* src = ei;
    const int* dst = ei + e;

    const int MM_SMEM = 128 * XP * 2 + 33792 + 2 * FF * 4;  // 69632
    const int LIN_SMEM = 128 * XP * 2 + 17408;              // 52224
    cudaFuncSetAttribute((const void*)k_mm<0, 0>, cudaFuncAttributeMaxDynamicSharedMemorySize, MM_SMEM);
    cudaFuncSetAttribute((const void*)k_mm<1, 0>, cudaFuncAttributeMaxDynamicSharedMemorySize, MM_SMEM);
    cudaFuncSetAttribute((const void*)k_mm<0, 1>, cudaFuncAttributeMaxDynamicSharedMemorySize, MM_SMEM);
    cudaFuncSetAttribute((const void*)k_lin, cudaFuncAttributeMaxDynamicSharedMemorySize, LIN_SMEM);

    const int B = 256;
    int nblk = (n + SB - 1) / SB;
    int wz_grid = (n + B - 1) / B;
    k_wpack<<<wz_grid, B>>>(gat_w, lin_w, n);
    k_deg_edges<<<(e + B - 1) / B, B>>>(dst, e);
    k_scan1<<<nblk, SB>>>(n);
    k_scan2<<<1, 1024>>>(n, nblk);
    k_scan3<<<nblk, SB>>>(signals, n);
    k_fill<<<(e + B - 1) / B, B>>>(src, dst, e);

    k_gcn_agg<<<(n + B - 1) / B, B>>>(n);
    k_gcn_x<<<(n + 63) / 64, 128>>>(gcn_w, gcn_b, n);  // + GN group-0 stats

    int grid_mm = (n + 127) / 128;
    int grid_at = (n + 7) / 8;
    for (int i = 0; i < NLAY; i++) {
        const float* aS = att_src + i * HH * CC;
        const float* aD = att_dst + i * HH * CC;
        if (i % GNFREQ == 0) {
            int g = i / GNFREQ;
            k_mm<1, 0><<<grid_mm, 256, MM_SMEM>>>(i, aS, aD, gn_w + g * FF,
                                                  gn_b + g * FF, gn_s + g * FF, g, n);
        } else if (i == NLAY - 1) {
            // layer 4: x was fp16-packed by layer-3 attn
            k_mm<0, 1><<<grid_mm, 256, MM_SMEM>>>(i, aS, aD, nullptr, nullptr, nullptr, 0, n);
        } else {
            k_mm<0, 0><<<grid_mm, 256, MM_SMEM>>>(i, aS, aD, nullptr, nullptr, nullptr, 0, n);
        }
        const float* gb = gat_b + i * FF;
        if (i == 2) {
            k_attn<1, 0, 0><<<grid_at, 256>>>(gb, n);  // + GN group-1 stats
        } else if (i == 3) {
            k_attn<0, 1, 0><<<grid_at, 256>>>(gb, n);  // fp16-pack x for layer 4
        } else if (i == NLAY - 1) {
            k_attn<0, 1, 1><<<grid_at, 256>>>(gb, n);  // fp16 residual in, fp16 out
        } else {
            k_attn<0, 0, 0><<<grid_at, 256>>>(gb, n);
        }
    }

    k_lin<<<grid_mm, 256, LIN_SMEM>>>(lin_b, (float*)d_out, n);
}